// round 17
// baseline (speedup 1.0000x reference)
#include <cuda_runtime.h>

// SparseEmbedding: out[b, :] = sum_n vals[b,n] * kernel[idx[b,n], :] + bias
// BATCH=4096, NNZ=32, VOCAB=1e6, DIM=64. float32 everywhere, idx int32.
//
// FINAL config (R8 structure, best measured 8.32us; run noise +-0.4us):
//   - one warp per batch row; lane l owns output dims [2l, 2l+1]
//   - ALL 32 row-gathers front-batched into registers via __ldcg
//     (L2-direct, MLP=32/warp) before any FMA consumer
//   - 256-thread CTAs, regs~80 -> 3 CTAs/SM, 24 warps/SM (measured-optimal
//     warps x MLP concurrency product)
//   - R16 tweak: TWO independent accumulators (even/odd nnz) halve the
//     serial FMA dependency chain in the epilogue (~64 cyc/warp saved)
//
// Floor analysis: 131072 random 256B gathers = 33.5MB compulsory traffic;
// at HBM3e random-granule efficiency + idx->gather ramp this is ~8.5us.
// Insensitive (measured) to: request path (LDG/L1, LDG.cg, LDG.256+evict,
// cp.async, TMA bulk, dual-path), cache policy (evict_first/last, stream),
// occupancy/MLP shape (16/32/64 x 8-32 warps/SM), wave structure
// (512 CTAs vs persistent 444). This is the hardware floor on this part.

#define BATCH 4096
#define NNZ   32
#define DIM   64

__global__ void __launch_bounds__(256, 1) sparse_embedding_kernel(
    const int*   __restrict__ idx,
    const float* __restrict__ vals,
    const float* __restrict__ table,
    const float* __restrict__ bias,
    float*       __restrict__ out)
{
    const int gwarp = (blockIdx.x * blockDim.x + threadIdx.x) >> 5;
    const int lane  = threadIdx.x & 31;

    // Each lane holds one (idx, val) pair for this row; broadcast via shfl.
    const int   my_idx = __ldg(idx  + gwarp * NNZ + lane);
    const float my_val = __ldg(vals + gwarp * NNZ + lane);

    // Phase 1: issue ALL 32 gather loads before any consumer (MLP=32/warp).
    // .cg -> L2-direct, no L1 lookup (zero cross-warp reuse).
    float2 kv[NNZ];
#pragma unroll
    for (int n = 0; n < NNZ; ++n) {
        const int id = __shfl_sync(0xffffffffu, my_idx, n);
        kv[n] = __ldcg(reinterpret_cast<const float2*>(
            table + (size_t)id * DIM) + lane);
    }

    // Phase 2: accumulate with two independent chains (even/odd nnz) to
    // halve the serial FMA dependency depth; bias folded into chain 0.
    float2 acc0 = __ldg(reinterpret_cast<const float2*>(bias) + lane);
    float2 acc1 = make_float2(0.0f, 0.0f);
#pragma unroll
    for (int n = 0; n < NNZ; n += 2) {
        const float v0 = __shfl_sync(0xffffffffu, my_val, n);
        const float v1 = __shfl_sync(0xffffffffu, my_val, n + 1);
        acc0.x = fmaf(v0, kv[n].x,     acc0.x);
        acc0.y = fmaf(v0, kv[n].y,     acc0.y);
        acc1.x = fmaf(v1, kv[n + 1].x, acc1.x);
        acc1.y = fmaf(v1, kv[n + 1].y, acc1.y);
    }
    acc0.x += acc1.x;
    acc0.y += acc1.y;

    reinterpret_cast<float2*>(out + (size_t)gwarp * DIM)[lane] = acc0;
}

extern "C" void kernel_launch(void* const* d_in, const int* in_sizes, int n_in,
                              void* d_out, int out_size)
{
    const int*   idx   = (const int*)  d_in[0];
    const float* vals  = (const float*)d_in[1];
    const float* table = (const float*)d_in[2];
    const float* bias  = (const float*)d_in[3];
    float*       out   = (float*)d_out;

    // 4096 warps, 8 warps per 256-thread CTA -> 512 CTAs.
    const int threads = 256;
    const int blocks  = (BATCH * 32) / threads;
    sparse_embedding_kernel<<<blocks, threads>>>(idx, vals, table, bias, out);
}